// round 2
// baseline (speedup 1.0000x reference)
#include <cuda_runtime.h>
#include <cstdint>

#define THREADS   512
#define CAP       4096          // candidate buffer capacity (uint64 keys)
#define KVAL      10
#define NCOLS     100000
#define NVEC      (NCOLS / 4)   // 25000 float4 per row

// Monotonic bijection fp32 -> uint32 preserving order (no NaNs in data).
__device__ __forceinline__ unsigned flip_f32(float f) {
    unsigned u = __float_as_uint(f);
    return (u & 0x80000000u) ? ~u : (u | 0x80000000u);
}
__device__ __forceinline__ float unflip_f32(unsigned u) {
    unsigned b = (u & 0x80000000u) ? (u ^ 0x80000000u) : ~u;
    return __uint_as_float(b);
}

// key = (flipped value << 32) | ~idx  -> uint64 max == larger value, then smaller index
__device__ __forceinline__ void push_cand(unsigned long long* buf, int* cnt,
                                          float v, int idx) {
    unsigned long long key =
        ((unsigned long long)flip_f32(v) << 32) | (unsigned)(~idx);
    int p = atomicAdd(cnt, 1);
    buf[p] = key;
}

__global__ __launch_bounds__(THREADS, 2)
void topk_kernel(const float* __restrict__ scores, float* __restrict__ out, int B) {
    __shared__ unsigned long long s_buf[CAP];
    __shared__ unsigned long long s_top[KVAL];
    __shared__ unsigned long long s_wbest[THREADS / 32];
    __shared__ int                s_wpos[THREADS / 32];
    __shared__ int                s_count;
    __shared__ float              s_thr;

    const int tid = threadIdx.x;
    const int row = blockIdx.x;
    const float4* __restrict__ r4 =
        (const float4*)(scores + (size_t)row * NCOLS);

    if (tid == 0) { s_count = 0; s_thr = -__int_as_float(0x7f800000); }
    __syncthreads();

    float thr = -__int_as_float(0x7f800000);  // -inf

    // ---- prune lambda: all THREADS threads participate; barrier-consistent on entry
    auto prune = [&]() {
        const int c = s_count;
        #pragma unroll 1
        for (int sel = 0; sel < KVAL; sel++) {
            unsigned long long best = 0ull;
            int bpos = -1;
            for (int j = tid; j < c; j += THREADS) {
                unsigned long long k = s_buf[j];
                if (k > best) { best = k; bpos = j; }
            }
            #pragma unroll
            for (int o = 16; o > 0; o >>= 1) {
                unsigned long long ob = __shfl_down_sync(0xffffffffu, best, o);
                int op               = __shfl_down_sync(0xffffffffu, bpos, o);
                if (ob > best) { best = ob; bpos = op; }
            }
            if ((tid & 31) == 0) {
                s_wbest[tid >> 5] = best;
                s_wpos [tid >> 5] = bpos;
            }
            __syncthreads();
            if (tid == 0) {
                unsigned long long bb = 0ull; int bp = -1;
                #pragma unroll
                for (int w = 0; w < THREADS / 32; w++)
                    if (s_wbest[w] > bb) { bb = s_wbest[w]; bp = s_wpos[w]; }
                s_top[sel] = bb;
                if (bp >= 0) s_buf[bp] = 0ull;   // remove winner
            }
            __syncthreads();
        }
        // compact: keep exactly the current top-10 as the surviving candidates
        if (tid < KVAL) s_buf[tid] = s_top[tid];
        if (tid == 0) {
            s_count = KVAL;
            s_thr   = unflip_f32((unsigned)(s_top[KVAL - 1] >> 32));
        }
        __syncthreads();
    };

    // ---- streaming main loop: 49 tiles of THREADS float4s
    for (int base = 0; base < NVEC; base += THREADS) {
        const int i = base + tid;
        if (i < NVEC) {
            float4 v = __ldcs(&r4[i]);
            float m = fmaxf(fmaxf(v.x, v.y), fmaxf(v.z, v.w));
            if (m >= thr) {                      // rare after first prune
                const int gi = i * 4;
                if (v.x >= thr) push_cand(s_buf, &s_count, v.x, gi + 0);
                if (v.y >= thr) push_cand(s_buf, &s_count, v.y, gi + 1);
                if (v.z >= thr) push_cand(s_buf, &s_count, v.z, gi + 2);
                if (v.w >= thr) push_cand(s_buf, &s_count, v.w, gi + 3);
            }
        }
        // two barriers => every thread reads the same s_count, before any new appends
        __syncthreads();
        const int c = s_count;
        __syncthreads();
        if (c >= CAP - THREADS * 4) prune();     // guarantee room for next full tile
        thr = s_thr;
    }

    // ---- final: ensure at least one prune happened & extract sorted top-10
    __syncthreads();
    prune();   // s_top[0..9] sorted descending, ties -> lowest index first

    if (tid < KVAL) {
        unsigned long long key = s_top[tid];
        float val = unflip_f32((unsigned)(key >> 32));
        int   idx = (int)(~(unsigned)key);
        // output layout: [B*K indices (as float)] then [B*K scores]
        out[(size_t)row * KVAL + tid]                        = (float)idx;
        out[(size_t)B * KVAL + (size_t)row * KVAL + tid]     = val;
    }
}

extern "C" void kernel_launch(void* const* d_in, const int* in_sizes, int n_in,
                              void* d_out, int out_size) {
    const float* scores = (const float*)d_in[0];
    const int B = in_sizes[0] / NCOLS;          // 2048
    (void)n_in; (void)out_size;
    topk_kernel<<<B, THREADS>>>(scores, (float*)d_out, B);
}